// round 5
// baseline (speedup 1.0000x reference)
#include <cuda_runtime.h>
#include <math.h>

#define F   128
#define TE  64          // edges per block
#define NT  256         // threads per block
#define KS  32          // K-slab for weight staging
#define HP  132         // padded row stride (floats) for 64xF tiles in smem
#define C0  0.31415926535897931f   // pi / LENGTH(=10)
#define MAXN 10016

// Scratch for A = inv_node @ phi_W1[:F] + phi_b1   (N x F)
__device__ float g_A[MAXN * F];

// ---------- f32x2 packed-FMA helpers ----------
__device__ __forceinline__ unsigned long long pack2(float x) {
    unsigned long long r;
    asm("mov.b64 %0, {%1, %1};" : "=l"(r) : "f"(x));
    return r;
}
__device__ __forceinline__ void ffma2(unsigned long long& d, unsigned long long a, unsigned long long b) {
    asm("fma.rn.f32x2 %0, %1, %2, %0;" : "+l"(d) : "l"(a), "l"(b));
}
__device__ __forceinline__ float2 unpack2(unsigned long long a) {
    float2 r;
    asm("mov.b64 {%0, %1}, %2;" : "=f"(r.x), "=f"(r.y) : "l"(a));
    return r;
}
__device__ __forceinline__ float silu(float x) { return x / (1.0f + expf(-x)); }

// ---------- Precompute A[n][j] = b1[j] + sum_k node[n][k] * phiW1[k][j] ----------
__global__ void precompA(const float* __restrict__ node, const float* __restrict__ W1,
                         const float* __restrict__ b1, int N) {
    __shared__ float xs[8][F];
    const int r0 = blockIdx.x * 8;
    const int tid = threadIdx.x;  // 128 threads
    for (int i = tid; i < 8 * F; i += 128) {
        int r = i >> 7, c = i & 127;
        xs[r][c] = (r0 + r < N) ? node[(size_t)(r0 + r) * F + c] : 0.f;
    }
    __syncthreads();
    const int j = tid;
    float acc[8];
    float b = b1[j];
#pragma unroll
    for (int i = 0; i < 8; i++) acc[i] = b;
    for (int k = 0; k < F; k++) {
        float w = W1[(size_t)k * F + j];
#pragma unroll
        for (int i = 0; i < 8; i++) acc[i] = fmaf(xs[i][k], w, acc[i]);
    }
#pragma unroll
    for (int i = 0; i < 8; i++)
        if (r0 + i < N) g_A[(size_t)(r0 + i) * F + j] = acc[i];
}

// ---------- Dual 64x128x32 GEMM slab (two independent A@B with shared tiling) ----------
// x1/x2: padded smem tiles, pre-offset to (tm*4)*HP + k0.
// wa/wb: smem slabs viewed as ulonglong2 (row k = 32 ulonglong2).
__device__ __forceinline__ void dual_gemm_slab(
    const float* __restrict__ x1, const float* __restrict__ x2,
    const ulonglong2* __restrict__ wa, const ulonglong2* __restrict__ wb,
    int tn,
    unsigned long long (&A1)[4][4], unsigned long long (&A2)[4][4])
{
#pragma unroll
    for (int kp = 0; kp < KS / 2; kp++) {
        const int k = 2 * kp;
        ulonglong2 a0  = wa[k * 32 + tn * 2];
        ulonglong2 a0b = wa[k * 32 + tn * 2 + 1];
        ulonglong2 a1r = wa[(k + 1) * 32 + tn * 2];
        ulonglong2 a1b = wa[(k + 1) * 32 + tn * 2 + 1];
        ulonglong2 b0  = wb[k * 32 + tn * 2];
        ulonglong2 b0b = wb[k * 32 + tn * 2 + 1];
        ulonglong2 b1r = wb[(k + 1) * 32 + tn * 2];
        ulonglong2 b1b = wb[(k + 1) * 32 + tn * 2 + 1];
#pragma unroll
        for (int i = 0; i < 4; i++) {
            float2 h1 = *(const float2*)(x1 + i * HP + k);
            float2 h2 = *(const float2*)(x2 + i * HP + k);
            unsigned long long p0 = pack2(h1.x), p1 = pack2(h1.y);
            unsigned long long q0 = pack2(h2.x), q1 = pack2(h2.y);
            ffma2(A1[i][0], p0, a0.x);  ffma2(A1[i][1], p0, a0.y);
            ffma2(A1[i][2], p0, a0b.x); ffma2(A1[i][3], p0, a0b.y);
            ffma2(A1[i][0], p1, a1r.x); ffma2(A1[i][1], p1, a1r.y);
            ffma2(A1[i][2], p1, a1b.x); ffma2(A1[i][3], p1, a1b.y);
            ffma2(A2[i][0], q0, b0.x);  ffma2(A2[i][1], q0, b0.y);
            ffma2(A2[i][2], q0, b0b.x); ffma2(A2[i][3], q0, b0b.y);
            ffma2(A2[i][0], q1, b1r.x); ffma2(A2[i][1], q1, b1r.y);
            ffma2(A2[i][2], q1, b1b.x); ffma2(A2[i][3], q1, b1b.y);
        }
    }
}

// smem budget (floats): DV 24576 | H1 8448 | H2 8448 | Wa 4096 | Wb 4096 | misc 448
#define SMEM_FLOATS (TE*F*3 + 2*TE*HP + 2*KS*F + 7*TE)
#define SMEM_BYTES  (SMEM_FLOATS * 4)

__global__ __launch_bounds__(NT, 1)
void edge_kernel(const int* __restrict__ ei,
                 const float* __restrict__ eq,
                 const float* __restrict__ invEdge,
                 const float* __restrict__ dist,
                 const float* __restrict__ edir,
                 const float* __restrict__ phiW1,
                 const float* __restrict__ phiW2, const float* __restrict__ phiB2,
                 const float* __restrict__ wW1,  const float* __restrict__ wB1,
                 const float* __restrict__ wW2,  const float* __restrict__ wB2,
                 float* __restrict__ outEq, float* __restrict__ outNode, float* __restrict__ outEdge,
                 int E)
{
    extern __shared__ __align__(16) float smem[];
    float* sDV = smem;                       // TE*F*3 (aliases sX1/sX2 during layer-1)
    float* sX1 = smem;                       // TE*HP
    float* sX2 = smem + TE * HP;             // TE*HP
    float* sH1 = smem + TE * F * 3;          // TE*HP
    float* sH2 = sH1 + TE * HP;              // TE*HP
    float* sWa = sH2 + TE * HP;              // KS*F
    float* sWb = sWa + KS * F;               // KS*F
    int*   sSrc = (int*)(sWb + KS * F);
    int*   sDst = sSrc + TE;
    float* sDist = (float*)(sDst + TE);
    float* sDir  = sDist + TE;               // TE*3

    const int tid = threadIdx.x;
    const int tn = tid & 15;                 // 16 col-groups of 8 cols
    const int tm = tid >> 4;                 // 16 row-groups of 4 rows
    const int j0 = tn * 8;
    const int e0 = blockIdx.x * TE;

    // ---- phase 1: per-edge scalars + inv_edge tile ----
    if (tid < TE) {
        int eg = e0 + tid;
        int s = 0, d = 0; float dd = 0.f, dx = 0.f, dy = 0.f, dz = 0.f;
        if (eg < E) {
            s = ei[eg]; d = ei[E + eg]; dd = dist[eg];
            dx = edir[eg * 3]; dy = edir[eg * 3 + 1]; dz = edir[eg * 3 + 2];
        }
        sSrc[tid] = s; sDst[tid] = d; sDist[tid] = dd;
        sDir[tid * 3] = dx; sDir[tid * 3 + 1] = dy; sDir[tid * 3 + 2] = dz;
    }
    for (int t = tid; t < TE * F / 4; t += NT) {
        int e = t >> 5, j4 = t & 31;
        int eg = e0 + e;
        float4 v = make_float4(0.f, 0.f, 0.f, 0.f);
        if (eg < E) v = *(const float4*)&invEdge[(size_t)eg * F + j4 * 4];
        *(float4*)&sX1[e * HP + j4 * 4] = v;
    }
    __syncthreads();

    // ---- positional encoding tile ----
    for (int t = tid; t < TE * F; t += NT) {
        int e = t >> 7, r = t & 127;
        float dd = sDist[e];
        int rr = r & 63;
        float arg = dd * (float)rr * C0;
        sX2[e * HP + r] = (r < 64) ? sinf(arg) : cosf(arg);
    }
    __syncthreads();

    // ---- layer 1: u_phi = X1 @ W1bot ; u_w = PE @ wW1 (dual) ----
    unsigned long long a1[4][4], a2[4][4];
#pragma unroll
    for (int i = 0; i < 4; i++)
#pragma unroll
        for (int cc = 0; cc < 4; cc++) { a1[i][cc] = 0ull; a2[i][cc] = 0ull; }

    for (int k0 = 0; k0 < F; k0 += KS) {
        __syncthreads();
        for (int t = tid; t < KS * F / 4; t += NT) {
            int k = t >> 5, j4 = t & 31;
            *(float4*)&sWa[k * F + j4 * 4] = *(const float4*)&phiW1[(size_t)(F + k0 + k) * F + j4 * 4];
            *(float4*)&sWb[k * F + j4 * 4] = *(const float4*)&wW1[(size_t)(k0 + k) * F + j4 * 4];
        }
        __syncthreads();
        dual_gemm_slab(sX1 + tm * 4 * HP + k0, sX2 + tm * 4 * HP + k0,
                       (const ulonglong2*)sWa, (const ulonglong2*)sWb, tn, a1, a2);
    }

    // layer-1 epilogue: h1 = silu(u_phi + A[src]), h2 = silu(u_w + w_b1)
    {
        float4 bwa = *(const float4*)&wB1[j0];
        float4 bwb = *(const float4*)&wB1[j0 + 4];
        float bw[8] = {bwa.x, bwa.y, bwa.z, bwa.w, bwb.x, bwb.y, bwb.z, bwb.w};
#pragma unroll
        for (int i = 0; i < 4; i++) {
            int e = tm * 4 + i;
            int src = sSrc[e];
            float4 Aa = *(const float4*)&g_A[(size_t)src * F + j0];
            float4 Ab = *(const float4*)&g_A[(size_t)src * F + j0 + 4];
            float av[8] = {Aa.x, Aa.y, Aa.z, Aa.w, Ab.x, Ab.y, Ab.z, Ab.w};
            float h1o[8], h2o[8];
#pragma unroll
            for (int cc = 0; cc < 4; cc++) {
                float2 u1 = unpack2(a1[i][cc]);
                float2 u2 = unpack2(a2[i][cc]);
                h1o[2 * cc]     = silu(u1.x + av[2 * cc]);
                h1o[2 * cc + 1] = silu(u1.y + av[2 * cc + 1]);
                h2o[2 * cc]     = silu(u2.x + bw[2 * cc]);
                h2o[2 * cc + 1] = silu(u2.y + bw[2 * cc + 1]);
            }
            *(float4*)&sH1[e * HP + j0]     = *(float4*)&h1o[0];
            *(float4*)&sH1[e * HP + j0 + 4] = *(float4*)&h1o[4];
            *(float4*)&sH2[e * HP + j0]     = *(float4*)&h2o[0];
            *(float4*)&sH2[e * HP + j0 + 4] = *(float4*)&h2o[4];
        }
    }

    // ---- layer 2: 5 gate chunks of 128 cols; m = (H1@phiW2+b) * (H2@wW2+b) ----
    for (int c = 0; c < 5; c++) {
        const int cb = c * F;
        unsigned long long aP[4][4], aW[4][4];
#pragma unroll
        for (int i = 0; i < 4; i++)
#pragma unroll
            for (int cc = 0; cc < 4; cc++) { aP[i][cc] = 0ull; aW[i][cc] = 0ull; }

        for (int k0 = 0; k0 < F; k0 += KS) {
            __syncthreads();
            for (int t = tid; t < KS * F / 4; t += NT) {
                int k = t >> 5, j4 = t & 31;
                *(float4*)&sWa[k * F + j4 * 4] = *(const float4*)&phiW2[(size_t)(k0 + k) * (5 * F) + cb + j4 * 4];
                *(float4*)&sWb[k * F + j4 * 4] = *(const float4*)&wW2[(size_t)(k0 + k) * (5 * F) + cb + j4 * 4];
            }
            __syncthreads();
            dual_gemm_slab(sH1 + tm * 4 * HP + k0, sH2 + tm * 4 * HP + k0,
                           (const ulonglong2*)sWa, (const ulonglong2*)sWb, tn, aP, aW);
        }

        // biases for this chunk
        float4 t0 = *(const float4*)&phiB2[cb + j0];
        float4 t1 = *(const float4*)&phiB2[cb + j0 + 4];
        float bp[8] = {t0.x, t0.y, t0.z, t0.w, t1.x, t1.y, t1.z, t1.w};
        float4 s0 = *(const float4*)&wB2[cb + j0];
        float4 s1 = *(const float4*)&wB2[cb + j0 + 4];
        float bq[8] = {s0.x, s0.y, s0.z, s0.w, s1.x, s1.y, s1.z, s1.w};

#pragma unroll
        for (int i = 0; i < 4; i++) {
            int e = tm * 4 + i;
            int eg = e0 + e;
            float m8[8];
#pragma unroll
            for (int cc = 0; cc < 4; cc++) {
                float2 p = unpack2(aP[i][cc]);
                float2 w = unpack2(aW[i][cc]);
                m8[2 * cc]     = (p.x + bp[2 * cc])     * (w.x + bq[2 * cc]);
                m8[2 * cc + 1] = (p.y + bp[2 * cc + 1]) * (w.y + bq[2 * cc + 1]);
            }
            float* dvp = &sDV[(e * F + j0) * 3];

            if (c == 0) {            // gates * eq[src]  (init dv)
                int src = sSrc[e];
                const float4* ep = (const float4*)&eq[(size_t)(src * F + j0) * 3];
                float ev[24], dvv[24];
#pragma unroll
                for (int q = 0; q < 6; q++) *(float4*)&ev[q * 4] = ep[q];
#pragma unroll
                for (int t = 0; t < 24; t++) dvv[t] = m8[t / 3] * ev[t];
#pragma unroll
                for (int q = 0; q < 6; q++) *(float4*)&dvp[q * 4] = *(float4*)&dvv[q * 4];
            } else if (c == 1) {     // cp_gates * cross(edir, eq[dst])
                int dst = sDst[e];
                float ax = sDir[e * 3], ay = sDir[e * 3 + 1], az = sDir[e * 3 + 2];
                const float4* ep = (const float4*)&eq[(size_t)(dst * F + j0) * 3];
                float ev[24], dvv[24];
#pragma unroll
                for (int q = 0; q < 6; q++) *(float4*)&ev[q * 4] = ep[q];
#pragma unroll
                for (int q = 0; q < 6; q++) *(float4*)&dvv[q * 4] = *(float4*)&dvp[q * 4];
#pragma unroll
                for (int jj = 0; jj < 8; jj++) {
                    float bx = ev[jj * 3], by = ev[jj * 3 + 1], bz = ev[jj * 3 + 2];
                    float g = m8[jj];
                    dvv[jj * 3 + 0] += g * (ay * bz - az * by);
                    dvv[jj * 3 + 1] += g * (az * bx - ax * bz);
                    dvv[jj * 3 + 2] += g * (ax * by - ay * bx);
                }
#pragma unroll
                for (int q = 0; q < 6; q++) *(float4*)&dvp[q * 4] = *(float4*)&dvv[q * 4];
            } else if (c == 2) {     // scale * edir
                float ax = sDir[e * 3], ay = sDir[e * 3 + 1], az = sDir[e * 3 + 2];
                float dvv[24];
#pragma unroll
                for (int q = 0; q < 6; q++) *(float4*)&dvv[q * 4] = *(float4*)&dvp[q * 4];
#pragma unroll
                for (int jj = 0; jj < 8; jj++) {
                    dvv[jj * 3 + 0] += m8[jj] * ax;
                    dvv[jj * 3 + 1] += m8[jj] * ay;
                    dvv[jj * 3 + 2] += m8[jj] * az;
                }
#pragma unroll
                for (int q = 0; q < 6; q++) *(float4*)&dvp[q * 4] = *(float4*)&dvv[q * 4];
            } else if (c == 3) {     // ds -> segment sum to outNode
                if (eg < E) {
                    float* base = outNode + (size_t)sDst[e] * F + j0;
#pragma unroll
                    for (int jj = 0; jj < 8; jj++) atomicAdd(base + jj, m8[jj]);
                }
            } else {                 // de -> outEdge = invEdge + de
                if (eg < E) {
                    float4 i0v = *(const float4*)&invEdge[(size_t)eg * F + j0];
                    float4 i1v = *(const float4*)&invEdge[(size_t)eg * F + j0 + 4];
                    float ie[8] = {i0v.x, i0v.y, i0v.z, i0v.w, i1v.x, i1v.y, i1v.z, i1v.w};
                    float o[8];
#pragma unroll
                    for (int jj = 0; jj < 8; jj++) o[jj] = ie[jj] + m8[jj];
                    *(float4*)&outEdge[(size_t)eg * F + j0]     = *(float4*)&o[0];
                    *(float4*)&outEdge[(size_t)eg * F + j0 + 4] = *(float4*)&o[4];
                }
            }
        }
    }

    // ---- flush dv -> outEq via coalesced atomics ----
    __syncthreads();
    for (int t = tid; t < TE * F * 3; t += NT) {
        int e = t / (F * 3);
        int r = t - e * (F * 3);
        if (e0 + e < E) atomicAdd(&outEq[(size_t)sDst[e] * (F * 3) + r], sDV[t]);
    }
}

extern "C" void kernel_launch(void* const* d_in, const int* in_sizes, int n_in,
                              void* d_out, int out_size) {
    const int*   ei      = (const int*)d_in[0];
    const float* invNode = (const float*)d_in[1];
    const float* eq      = (const float*)d_in[2];
    const float* invEdge = (const float*)d_in[3];
    const float* dist    = (const float*)d_in[4];
    const float* edir    = (const float*)d_in[5];
    const float* phiW1   = (const float*)d_in[6];
    const float* phiB1   = (const float*)d_in[7];
    const float* phiW2   = (const float*)d_in[8];
    const float* phiB2   = (const float*)d_in[9];
    const float* wW1     = (const float*)d_in[10];
    const float* wB1     = (const float*)d_in[11];
    const float* wW2     = (const float*)d_in[12];
    const float* wB2     = (const float*)d_in[13];

    const int E = in_sizes[0] / 2;
    const int N = in_sizes[1] / F;

    float* outEq   = (float*)d_out;
    float* outNode = outEq + (size_t)N * F * 3;
    float* outEdge = outNode + (size_t)N * F;

    // initialize node outputs with base values (edge output fully overwritten)
    cudaMemcpyAsync(outEq, eq, (size_t)N * F * 3 * sizeof(float),
                    cudaMemcpyDeviceToDevice, 0);
    cudaMemcpyAsync(outNode, invNode, (size_t)N * F * sizeof(float),
                    cudaMemcpyDeviceToDevice, 0);

    // A = inv_node @ phiW1_top + phi_b1
    precompA<<<(N + 7) / 8, 128, 0, 0>>>(invNode, phiW1, phiB1, N);

    cudaFuncSetAttribute(edge_kernel, cudaFuncAttributeMaxDynamicSharedMemorySize, SMEM_BYTES);
    const int nb = (E + TE - 1) / TE;
    edge_kernel<<<nb, NT, SMEM_BYTES, 0>>>(ei, eq, invEdge, dist, edir,
                                           phiW1, phiW2, phiB2,
                                           wW1, wB1, wW2, wB2,
                                           outEq, outNode, outEdge, E);
}